// round 15
// baseline (speedup 1.0000x reference)
#include <cuda_runtime.h>

#define VV   128
#define HH   512
#define BB   8192
#define OUTW 256   // 2*V

#define VG    8            // v's per GEMM block
#define KT    32           // k's per GEMM block
#define KS2   (HH / KT)    // 16 k-segments
#define VGN2  (VV / VG)    // 16 v-groups
#define NGEMM 256          // 16 vg x 16 ks
#define NZERO 256
#define THR   256

// Scratch (alloc-free rule: __device__ globals). g_vgdone monotonic -> graph
// replay safe; tables identical every replay.
__device__ float    g_part[KS2 * VV * OUTW];   // 2 MB partial sums
__device__ int      g_loc[VV];
__device__ int      g_scale[VV];
__device__ unsigned g_vgdone[VGN2];            // 16 increments per vg/replay

// Monotone orderable key for float argmax with first-index tie-break.
__device__ __forceinline__ unsigned long long amax_key(float f, int col)
{
    unsigned int u = __float_as_uint(f);
    u = (u & 0x80000000u) ? ~u : (u | 0x80000000u);
    return ((unsigned long long)u << 32) | (unsigned long long)(127 - col);
}

__device__ __forceinline__ void cp_async16(void* smem_dst, const void* gmem_src)
{
    unsigned long long sa = __cvta_generic_to_shared(smem_dst);
    asm volatile("cp.async.cg.shared.global [%0], [%1], 16;\n"
                 :: "r"((unsigned)sa), "l"(gmem_src) : "memory");
}

// ---------------------------------------------------------------------------
// K1: blocks 0..255 compute the (loc, scale) tables (GEMM + argmax);
//     blocks 256..511 zero-fill the ENTIRE output (8 MB of constant stores,
//     no load dependency, overlapping the GEMM). No inter-duty sync needed:
//     the kernel boundary orders K2's scatters after both duties.
// ---------------------------------------------------------------------------
__global__ void __launch_bounds__(THR)
k1_tables_zero(const float* __restrict__ W1, const float* __restrict__ b1,
               const float* __restrict__ W2, const float* __restrict__ b2,
               float* __restrict__ out)
{
    const int blk = blockIdx.x;
    const int t = threadIdx.x;

    if (blk >= NGEMM) {
        // ================= zero duty: pure constant STG.128 =================
        // 8 MB = 524288 float4; 256 blocks x 256 thr x 8 float4.
        float4* o4 = reinterpret_cast<float4*>(out);
        const int base = (blk - NGEMM) * THR + t;     // 0..65535
        const float4 z4 = make_float4(0.f, 0.f, 0.f, 0.f);
        #pragma unroll
        for (int i = 0; i < 8; ++i)
            o4[base + i * (NZERO * THR)] = z4;
        return;
    }

    // ===================== GEMM duty ========================================
    const int wid = t >> 5, lane = t & 31;
    const int vg = blk & (VGN2 - 1);   // 0..15
    const int ks = blk >> 4;           // 0..15
    const int v0 = vg * VG;
    const int k0 = ks * KT;
    const int c = t;

    __shared__ __align__(16) float smW2[KT][OUTW];   // 32 KB
    __shared__ __align__(16) float h[KT][VG];        // 1 KB
    __shared__ unsigned long long skey[VG * 2];
    __shared__ int s_last;

    // Stage W2 tile [k0,k0+32) x 256 via cp.async (HW-pipelined, zero regs).
    {
        const float4* __restrict__ g4 =
            reinterpret_cast<const float4*>(W2 + (size_t)k0 * OUTW);
        float4* s4 = reinterpret_cast<float4*>(&smW2[0][0]);
        #pragma unroll
        for (int i = 0; i < 8; ++i)
            cp_async16(&s4[t + i * THR], &g4[t + i * THR]);
        asm volatile("cp.async.commit_group;\n" ::: "memory");
    }

    // h[k][v] = relu(W1[v0+v][k0+k] + b1[k0+k]); 256 entries, 1/thread.
    {
        const int v = t >> 5, k = t & (KT - 1);
        h[k][v] = fmaxf(W1[(size_t)(v0 + v) * HH + k0 + k] + b1[k0 + k], 0.0f);
    }
    if (t < VG * 2) skey[t] = 0ULL;

    asm volatile("cp.async.wait_group 0;\n" ::: "memory");
    __syncthreads();

    // Thread-per-column accumulate from SMEM (29-cyc latency).
    float acc[VG];
    #pragma unroll
    for (int v = 0; v < VG; ++v) acc[v] = 0.0f;

    #pragma unroll 4
    for (int k = 0; k < KT; ++k) {
        const float w = smW2[k][c];                       // conflict-free LDS
        const float4 h03 = *reinterpret_cast<const float4*>(&h[k][0]);
        const float4 h47 = *reinterpret_cast<const float4*>(&h[k][4]);
        acc[0] = fmaf(h03.x, w, acc[0]);
        acc[1] = fmaf(h03.y, w, acc[1]);
        acc[2] = fmaf(h03.z, w, acc[2]);
        acc[3] = fmaf(h03.w, w, acc[3]);
        acc[4] = fmaf(h47.x, w, acc[4]);
        acc[5] = fmaf(h47.y, w, acc[5]);
        acc[6] = fmaf(h47.z, w, acc[6]);
        acc[7] = fmaf(h47.w, w, acc[7]);
    }

    #pragma unroll
    for (int v = 0; v < VG; ++v)                          // coalesced per v
        g_part[((size_t)ks * VV + v0 + v) * OUTW + c] = acc[v];

    // ---- vgroup completion: 16th arriver reduces + argmaxes its 8 v's ------
    if (t == 0) {
        __threadfence();                                  // release partials
        const unsigned my = atomicAdd(&g_vgdone[vg], 1u);
        s_last = ((my & (KS2 - 1u)) == (KS2 - 1u));
    }
    __syncthreads();

    if (s_last) {
        const float bb = b2[c];
        const int half = c >> 7;                          // warp-uniform
        const int col = c & 127;

        #pragma unroll
        for (int v = 0; v < VG; ++v) {
            float ps[KS2];
            #pragma unroll
            for (int s8 = 0; s8 < KS2; ++s8)              // 16 indep loads
                ps[s8] = g_part[((size_t)s8 * VV + v0 + v) * OUTW + c];
            float sum = bb;
            #pragma unroll
            for (int s8 = 0; s8 < KS2; ++s8) sum += ps[s8];

            unsigned long long key = amax_key(sum, col);
            #pragma unroll
            for (int off = 16; off > 0; off >>= 1) {
                const unsigned long long o = __shfl_xor_sync(0xFFFFFFFFu, key, off);
                if (o > key) key = o;
            }
            if (lane == 0) atomicMax(&skey[v * 2 + half], key);
        }
        __syncthreads();

        if (t < VG) {
            g_loc[v0 + t]   = 127 - (int)(skey[t * 2]     & 0xFFFFFFFFULL);
            g_scale[v0 + t] = 127 - (int)(skey[t * 2 + 1] & 0xFFFFFFFFULL);
        }
    }
}

// ---------------------------------------------------------------------------
// K2: extract + scatter. 256 blocks x 256 thr; 8 warps x 4 rows.
// Read-only on the input (front-batched, MLP 8); per row writes just TWO
// floats into the pre-zeroed output: out[b][i0]=1 and the flow one-hot.
// x0/x1 are EXACT one-hots -> index = reduce_add of lane contributions.
// ---------------------------------------------------------------------------
__global__ void __launch_bounds__(THR)
k2_extract(const float* __restrict__ in, float* __restrict__ out)
{
    const int t = threadIdx.x;
    const int wid = t >> 5, lane = t & 31;
    const int r0 = blockIdx.x * 32 + wid * 4;

    const float4* in4 = reinterpret_cast<const float4*>(in);

    float4 a[4], c4[4];
    #pragma unroll
    for (int i = 0; i < 4; ++i) {       // front-batched: MLP 8
        const size_t base = (size_t)(r0 + i) * 64;
        a[i] = in4[base + lane];
        c4[i] = in4[base + 32 + lane];
    }

    int my_i0 = 0, my_i1 = 0;
    #pragma unroll
    for (int i = 0; i < 4; ++i) {
        const int m0 = (a[i].x == 1.0f) | ((a[i].y == 1.0f) << 1) |
                       ((a[i].z == 1.0f) << 2) | ((a[i].w == 1.0f) << 3);
        const int m1 = (c4[i].x == 1.0f) | ((c4[i].y == 1.0f) << 1) |
                       ((c4[i].z == 1.0f) << 2) | ((c4[i].w == 1.0f) << 3);

        const int li0 = m0 ? (lane * 4 + __ffs(m0) - 1) : 0;
        const int li1 = m1 ? (lane * 4 + __ffs(m1) - 1) : 0;
        const int i0 = __reduce_add_sync(0xFFFFFFFFu, li0);
        const int i1 = __reduce_add_sync(0xFFFFFFFFu, li1);
        if (lane == i) { my_i0 = i0; my_i1 = i1; }
    }

    // Lanes 0..3 finish their own row: table lookup + two 4-byte stores.
    if (lane < 4) {
        const int row = r0 + lane;
        const int l = g_loc[my_i0];
        const int s = g_scale[my_i0];
        float* orow = out + (size_t)row * OUTW;
        orow[my_i0] = 1.0f;                               // x0 reconstructed
        if (s != 0) {
            const int tcol = (l + my_i1 * s) & (VV - 1);
            orow[VV + tcol] = 1.0f;
        }
    }
}

// ---------------------------------------------------------------------------
// Launch: K1 (tables || zero-fill) then K2 (extract + 2-float scatter).
// Inputs in setup_inputs() order: inputs, W1, b1, W2, b2.
// ---------------------------------------------------------------------------
extern "C" void kernel_launch(void* const* d_in, const int* in_sizes, int n_in,
                              void* d_out, int out_size)
{
    const float* in = (const float*)d_in[0];
    const float* W1 = (const float*)d_in[1];
    const float* b1 = (const float*)d_in[2];
    const float* W2 = (const float*)d_in[3];
    const float* b2 = (const float*)d_in[4];
    float* out = (float*)d_out;

    k1_tables_zero<<<NGEMM + NZERO, THR>>>(W1, b1, W2, b2, out);
    k2_extract<<<BB / 32, THR>>>(in, out);
}